// round 11
// baseline (speedup 1.0000x reference)
#include <cuda_runtime.h>
#include <cstdint>

#define XS 128
#define BATCH 8
#define GRID_ELEMS (BATCH * XS * XS * XS)   // 16,777,216 floats = 67 MB (fits L2)

__device__ __align__(128) float g_grid[GRID_ELEMS];

// ---------------------------------------------------------------------------
// Kernel 1: zero the grid, grid-stride, 1 block per SM (148 x 1024).
// LTS-store-bound, so fewer threads run at the same ~11us — but leave 1024
// thread-slots per SM free so the PDL-launched scatter blocks become
// resident immediately and overlap their DRAM input loads with the zeroing.
// ---------------------------------------------------------------------------
__global__ void zero_kernel(float* __restrict__ d_out, int out_size) {
    cudaTriggerProgrammaticLaunchCompletion();
    const int nthr = 148 * 1024;
    int t = blockIdx.x * blockDim.x + threadIdx.x;
    float4 z = make_float4(0.f, 0.f, 0.f, 0.f);
    float4* g4 = reinterpret_cast<float4*>(g_grid);
    #pragma unroll 4
    for (int i = t; i < GRID_ELEMS / 4; i += nthr)   // 4,194,304 float4
        g4[i] = z;
    if (t < 16 && t < out_size) d_out[t] = 0.f;
}

// ---------------------------------------------------------------------------
// Kernel 2: scatter-add, 4 points per thread, PDL-overlapped with zeroing.
// Input loads (independent of the grid) issue BEFORE
// cudaGridDependencySynchronize(); atomics to the grid only after it.
// __ldcs: stream inputs through L2 without evicting the grid.
// ---------------------------------------------------------------------------
__global__ void scatter_kernel(const int4* __restrict__ idx4,
                               const float4* __restrict__ val4) {
    int t = blockIdx.x * blockDim.x + threadIdx.x;   // 0 .. 524287
    int b = t >> 16;                                 // 65536 threads per batch
    int4 a = __ldcs(idx4 + 3 * t);                   // x0 y0 z0 x1
    int4 c = __ldcs(idx4 + 3 * t + 1);               // y1 z1 x2 y2
    int4 e = __ldcs(idx4 + 3 * t + 2);               // z2 x3 y3 z3
    float4 v = __ldcs(val4 + t);

    cudaGridDependencySynchronize();                 // wait: grid fully zeroed

    float* gb = g_grid + (b << 21);
    atomicAdd(gb + ((a.x << 14) | (a.y << 7) | a.z), v.x);
    atomicAdd(gb + ((a.w << 14) | (c.x << 7) | c.y), v.y);
    atomicAdd(gb + ((c.z << 14) | (c.w << 7) | e.x), v.z);
    atomicAdd(gb + ((e.y << 14) | (e.z << 7) | e.w), v.w);
}

// ---------------------------------------------------------------------------
// Packed f32x2 diff accumulator: 4 diffs of (a - b) -> tv halves + packed mse.
// Sign of the diff is irrelevant for |d| and d*d, so d = fma(b, -1, a).
// ---------------------------------------------------------------------------
__device__ __forceinline__ void acc4(const float4 a, const float4 bv,
                                     unsigned long long neg1,
                                     float& tv0, float& tv1,
                                     unsigned long long& m2a,
                                     unsigned long long& m2b) {
    unsigned long long axy, azw, bxy, bzw, d0, d1;
    asm("mov.b64 %0, {%1,%2};" : "=l"(axy) : "f"(a.x),  "f"(a.y));
    asm("mov.b64 %0, {%1,%2};" : "=l"(azw) : "f"(a.z),  "f"(a.w));
    asm("mov.b64 %0, {%1,%2};" : "=l"(bxy) : "f"(bv.x), "f"(bv.y));
    asm("mov.b64 %0, {%1,%2};" : "=l"(bzw) : "f"(bv.z), "f"(bv.w));
    asm("fma.rn.f32x2 %0, %1, %2, %3;" : "=l"(d0) : "l"(bxy), "l"(neg1), "l"(axy));
    asm("fma.rn.f32x2 %0, %1, %2, %3;" : "=l"(d1) : "l"(bzw), "l"(neg1), "l"(azw));
    asm("fma.rn.f32x2 %0, %1, %1, %0;" : "+l"(m2a) : "l"(d0));
    asm("fma.rn.f32x2 %0, %1, %1, %0;" : "+l"(m2b) : "l"(d1));
    float e0, e1, e2, e3;
    asm("mov.b64 {%0,%1}, %2;" : "=f"(e0), "=f"(e1) : "l"(d0));
    asm("mov.b64 {%0,%1}, %2;" : "=f"(e2), "=f"(e3) : "l"(d1));
    tv0 += fabsf(e0); tv1 += fabsf(e1);
    tv0 += fabsf(e2); tv1 += fabsf(e3);
}

// ---------------------------------------------------------------------------
// Kernel 3: fused TV + MSE reduction. 8-wide z strips, predicate-free edges.
// Block = 128 thr = 16 z-slots x 8 j-rows. 16 owned i-planes + clamped halo.
// Grid: 8 b x 16 jc x 8 ic = 1024 blocks. No __syncthreads in the loop.
// ---------------------------------------------------------------------------
__global__ void reduce_kernel(float* __restrict__ d_out) {
    __shared__ float stv[4], smse[4];

    int tid = threadIdx.x;
    int zs  = tid & 15;          // z slot: z = 8*zs .. 8*zs+7
    int jl  = tid >> 4;          // 0..7 local j
    int bx  = blockIdx.x;
    int b   = bx >> 7;
    int jc  = (bx >> 3) & 15;
    int ic  = bx & 7;
    int i0  = ic << 4;
    int j   = (jc << 3) + jl;

    const float* colp = g_grid + ((size_t)b << 21) + (j << 7) + (zs << 3);
    // y-neighbor column: row j+1, clamped at the global edge (diffs -> 0)
    const float* coly = (j < 127) ? colp + 128 : colp;
    bool zseam = (zs < 15);

    unsigned long long neg1;
    asm("mov.b64 %0, {%1,%2};" : "=l"(neg1) : "f"(-1.0f), "f"(-1.0f));

    float tv0 = 0.f, tv1 = 0.f;
    unsigned long long m2a = 0ull, m2b = 0ull;

    float4 c0 = *reinterpret_cast<const float4*>(colp + ((size_t)i0 << 14));
    float4 c1 = *reinterpret_cast<const float4*>(colp + ((size_t)i0 << 14) + 4);
    float4 y0 = *reinterpret_cast<const float4*>(coly + ((size_t)i0 << 14));
    float4 y1 = *reinterpret_cast<const float4*>(coly + ((size_t)i0 << 14) + 4);

    #pragma unroll 4
    for (int ii = 0; ii < 16; ii++) {
        int inext  = i0 + ii + 1;
        int iclamp = (inext <= 127) ? inext : 127;   // clamp -> x-diff 0
        size_t off = (size_t)iclamp << 14;
        float4 n0 = *reinterpret_cast<const float4*>(colp + off);
        float4 n1 = *reinterpret_cast<const float4*>(colp + off + 4);
        float4 w0 = *reinterpret_cast<const float4*>(coly + off);
        float4 w1 = *reinterpret_cast<const float4*>(coly + off + 4);

        // z-diffs: shifted vectors; seam from next z-slot (lane+1)
        float nx = __shfl_down_sync(0xffffffffu, c0.x, 1);
        if (!zseam) nx = c1.w;                       // clamp -> diff 0
        float4 s0 = make_float4(c0.y, c0.z, c0.w, c1.x);
        float4 s1 = make_float4(c1.y, c1.z, c1.w, nx);
        acc4(s0, c0, neg1, tv0, tv1, m2a, m2b);
        acc4(s1, c1, neg1, tv0, tv1, m2a, m2b);
        // y-diffs
        acc4(y0, c0, neg1, tv0, tv1, m2a, m2b);
        acc4(y1, c1, neg1, tv0, tv1, m2a, m2b);
        // x-diffs
        acc4(n0, c0, neg1, tv0, tv1, m2a, m2b);
        acc4(n1, c1, neg1, tv0, tv1, m2a, m2b);

        c0 = n0; c1 = n1; y0 = w0; y1 = w1;
    }

    float ma0, ma1, mb0, mb1;
    asm("mov.b64 {%0,%1}, %2;" : "=f"(ma0), "=f"(ma1) : "l"(m2a));
    asm("mov.b64 {%0,%1}, %2;" : "=f"(mb0), "=f"(mb1) : "l"(m2b));
    float tv  = tv0 + tv1;
    float mse = (ma0 + ma1) + (mb0 + mb1);

    // block reduction: warp shuffle -> shared -> single atomicAdd
    #pragma unroll
    for (int o = 16; o; o >>= 1) {
        tv  += __shfl_down_sync(0xffffffffu, tv,  o);
        mse += __shfl_down_sync(0xffffffffu, mse, o);
    }
    int lane = tid & 31, w = tid >> 5;
    if (lane == 0) { stv[w] = tv; smse[w] = mse; }
    __syncthreads();
    if (tid == 0) {
        float TV = stv[0] + stv[1] + stv[2] + stv[3];
        float MS = smse[0] + smse[1] + smse[2] + smse[3];
        const float inv_tv  = 1.f / 2097152.f;   // xsize^3
        const float inv_mse = 1.f / 32512.f;     // 2*128*128 - 2*128
        atomicAdd(&d_out[b],     TV * inv_tv);
        atomicAdd(&d_out[8 + b], MS * inv_mse);
    }
}

// ---------------------------------------------------------------------------
extern "C" void kernel_launch(void* const* d_in, const int* in_sizes, int n_in,
                              void* d_out, int out_size) {
    const int4*   idx4 = (const int4*)d_in[0];    // [B, N, 3] int32
    const float4* val4 = (const float4*)d_in[1];  // [B, N] float32
    float* out = (float*)d_out;                   // tv[8] ++ mse[8]

    zero_kernel<<<148, 1024>>>(out, out_size);    // 1 block/SM, grid-stride

    // Scatter with Programmatic Dependent Launch: becomes resident while
    // zero runs, loads inputs, then griddepsyncs before touching the grid.
    cudaLaunchConfig_t cfg = {};
    cfg.gridDim  = dim3(2048);
    cfg.blockDim = dim3(256);
    cfg.dynamicSmemBytes = 0;
    cfg.stream = 0;
    cudaLaunchAttribute at[1];
    at[0].id = cudaLaunchAttributeProgrammaticStreamSerialization;
    at[0].val.programmaticStreamSerializationAllowed = 1;
    cfg.attrs = at;
    cfg.numAttrs = 1;
    cudaLaunchKernelEx(&cfg, scatter_kernel, idx4, val4);

    reduce_kernel<<<1024, 128>>>(out);            // 8b x 16jc x 8ic strips
}

// round 14
// speedup vs baseline: 1.0073x; 1.0073x over previous
#include <cuda_runtime.h>
#include <cstdint>

#define XS 128
#define BATCH 8
#define GRID_ELEMS (BATCH * XS * XS * XS)   // 16,777,216 floats = 67 MB (fits L2)

__device__ __align__(128) float g_grid[GRID_ELEMS];

// ---------------------------------------------------------------------------
// Kernel 1: zero the grid (2x float4 per thread) + zero the 16 output accums.
// Full-occupancy LSU store kernel — measured fastest mechanism (~11us,
// L2 store-path cap). PDL-triggers scatter at entry; overlap happens on the
// retirement ramp.
// ---------------------------------------------------------------------------
__global__ void zero_kernel(float* __restrict__ d_out, int out_size) {
    cudaTriggerProgrammaticLaunchCompletion();
    int t = blockIdx.x * blockDim.x + threadIdx.x;   // 0 .. 2097151
    float4 z = make_float4(0.f, 0.f, 0.f, 0.f);
    float4* g4 = reinterpret_cast<float4*>(g_grid);
    g4[t]           = z;
    g4[t + 2097152] = z;
    if (t < 16 && t < out_size) d_out[t] = 0.f;
}

// ---------------------------------------------------------------------------
// Kernel 2: scatter-add, 4 points per thread, PDL-overlapped with zeroing.
// Input loads issue BEFORE cudaGridDependencySynchronize(); grid atomics
// after. __ldcs streams inputs through L2 without evicting the grid.
// ---------------------------------------------------------------------------
__global__ void scatter_kernel(const int4* __restrict__ idx4,
                               const float4* __restrict__ val4) {
    int t = blockIdx.x * blockDim.x + threadIdx.x;   // 0 .. 524287
    int b = t >> 16;                                 // 65536 threads per batch
    int4 a = __ldcs(idx4 + 3 * t);                   // x0 y0 z0 x1
    int4 c = __ldcs(idx4 + 3 * t + 1);               // y1 z1 x2 y2
    int4 e = __ldcs(idx4 + 3 * t + 2);               // z2 x3 y3 z3
    float4 v = __ldcs(val4 + t);

    cudaGridDependencySynchronize();                 // wait: grid fully zeroed

    float* gb = g_grid + (b << 21);
    atomicAdd(gb + ((a.x << 14) | (a.y << 7) | a.z), v.x);
    atomicAdd(gb + ((a.w << 14) | (c.x << 7) | c.y), v.y);
    atomicAdd(gb + ((c.z << 14) | (c.w << 7) | e.x), v.z);
    atomicAdd(gb + ((e.y << 14) | (e.z << 7) | e.w), v.w);
}

// ---------------------------------------------------------------------------
// Packed f32x2 diff accumulator: 4 diffs of (a - b) -> tv halves + packed mse.
// Sign of the diff is irrelevant for |d| and d*d, so d = fma(b, -1, a).
// ---------------------------------------------------------------------------
__device__ __forceinline__ void acc4(const float4 a, const float4 bv,
                                     unsigned long long neg1,
                                     float& tv0, float& tv1,
                                     unsigned long long& m2a,
                                     unsigned long long& m2b) {
    unsigned long long axy, azw, bxy, bzw, d0, d1;
    asm("mov.b64 %0, {%1,%2};" : "=l"(axy) : "f"(a.x),  "f"(a.y));
    asm("mov.b64 %0, {%1,%2};" : "=l"(azw) : "f"(a.z),  "f"(a.w));
    asm("mov.b64 %0, {%1,%2};" : "=l"(bxy) : "f"(bv.x), "f"(bv.y));
    asm("mov.b64 %0, {%1,%2};" : "=l"(bzw) : "f"(bv.z), "f"(bv.w));
    asm("fma.rn.f32x2 %0, %1, %2, %3;" : "=l"(d0) : "l"(bxy), "l"(neg1), "l"(axy));
    asm("fma.rn.f32x2 %0, %1, %2, %3;" : "=l"(d1) : "l"(bzw), "l"(neg1), "l"(azw));
    asm("fma.rn.f32x2 %0, %1, %1, %0;" : "+l"(m2a) : "l"(d0));
    asm("fma.rn.f32x2 %0, %1, %1, %0;" : "+l"(m2b) : "l"(d1));
    float e0, e1, e2, e3;
    asm("mov.b64 {%0,%1}, %2;" : "=f"(e0), "=f"(e1) : "l"(d0));
    asm("mov.b64 {%0,%1}, %2;" : "=f"(e2), "=f"(e3) : "l"(d1));
    tv0 += fabsf(e0); tv1 += fabsf(e1);
    tv0 += fabsf(e2); tv1 += fabsf(e3);
}

// ---------------------------------------------------------------------------
// Kernel 3: fused TV + MSE reduction. 8-wide z strips, predicate-free edges.
// Block = 128 thr = 16 z-slots x 8 j-rows, 8 owned i-planes (+ clamped halo).
// 2048 blocks = 8 b x 16 jc x 16 ic -> 2x the independent load streams of
// the previous 16-plane version (latency-bound fix), fully unrolled.
// ---------------------------------------------------------------------------
__global__ void reduce_kernel(float* __restrict__ d_out) {
    __shared__ float stv[4], smse[4];

    int tid = threadIdx.x;
    int zs  = tid & 15;          // z slot: z = 8*zs .. 8*zs+7
    int jl  = tid >> 4;          // 0..7 local j
    int bx  = blockIdx.x;
    int b   = bx >> 8;           // 256 blocks per batch
    int jc  = (bx >> 4) & 15;
    int ic  = bx & 15;
    int i0  = ic << 3;           // 8-plane chunk
    int j   = (jc << 3) + jl;

    const float* colp = g_grid + ((size_t)b << 21) + (j << 7) + (zs << 3);
    // y-neighbor column: row j+1, clamped at the global edge (diffs -> 0)
    const float* coly = (j < 127) ? colp + 128 : colp;
    bool zseam = (zs < 15);

    unsigned long long neg1;
    asm("mov.b64 %0, {%1,%2};" : "=l"(neg1) : "f"(-1.0f), "f"(-1.0f));

    float tv0 = 0.f, tv1 = 0.f;
    unsigned long long m2a = 0ull, m2b = 0ull;

    float4 c0 = *reinterpret_cast<const float4*>(colp + ((size_t)i0 << 14));
    float4 c1 = *reinterpret_cast<const float4*>(colp + ((size_t)i0 << 14) + 4);
    float4 y0 = *reinterpret_cast<const float4*>(coly + ((size_t)i0 << 14));
    float4 y1 = *reinterpret_cast<const float4*>(coly + ((size_t)i0 << 14) + 4);

    #pragma unroll
    for (int ii = 0; ii < 8; ii++) {
        int inext  = i0 + ii + 1;
        int iclamp = (inext <= 127) ? inext : 127;   // clamp -> x-diff 0
        size_t off = (size_t)iclamp << 14;
        float4 n0 = *reinterpret_cast<const float4*>(colp + off);
        float4 n1 = *reinterpret_cast<const float4*>(colp + off + 4);
        float4 w0 = *reinterpret_cast<const float4*>(coly + off);
        float4 w1 = *reinterpret_cast<const float4*>(coly + off + 4);

        // z-diffs: shifted vectors; seam from next z-slot (lane+1)
        float nx = __shfl_down_sync(0xffffffffu, c0.x, 1);
        if (!zseam) nx = c1.w;                       // clamp -> diff 0
        float4 s0 = make_float4(c0.y, c0.z, c0.w, c1.x);
        float4 s1 = make_float4(c1.y, c1.z, c1.w, nx);
        acc4(s0, c0, neg1, tv0, tv1, m2a, m2b);
        acc4(s1, c1, neg1, tv0, tv1, m2a, m2b);
        // y-diffs
        acc4(y0, c0, neg1, tv0, tv1, m2a, m2b);
        acc4(y1, c1, neg1, tv0, tv1, m2a, m2b);
        // x-diffs
        acc4(n0, c0, neg1, tv0, tv1, m2a, m2b);
        acc4(n1, c1, neg1, tv0, tv1, m2a, m2b);

        c0 = n0; c1 = n1; y0 = w0; y1 = w1;
    }

    float ma0, ma1, mb0, mb1;
    asm("mov.b64 {%0,%1}, %2;" : "=f"(ma0), "=f"(ma1) : "l"(m2a));
    asm("mov.b64 {%0,%1}, %2;" : "=f"(mb0), "=f"(mb1) : "l"(m2b));
    float tv  = tv0 + tv1;
    float mse = (ma0 + ma1) + (mb0 + mb1);

    // block reduction: warp shuffle -> shared -> single atomicAdd
    #pragma unroll
    for (int o = 16; o; o >>= 1) {
        tv  += __shfl_down_sync(0xffffffffu, tv,  o);
        mse += __shfl_down_sync(0xffffffffu, mse, o);
    }
    int lane = tid & 31, w = tid >> 5;
    if (lane == 0) { stv[w] = tv; smse[w] = mse; }
    __syncthreads();
    if (tid == 0) {
        float TV = stv[0] + stv[1] + stv[2] + stv[3];
        float MS = smse[0] + smse[1] + smse[2] + smse[3];
        const float inv_tv  = 1.f / 2097152.f;   // xsize^3
        const float inv_mse = 1.f / 32512.f;     // 2*128*128 - 2*128
        atomicAdd(&d_out[b],     TV * inv_tv);
        atomicAdd(&d_out[8 + b], MS * inv_mse);
    }
}

// ---------------------------------------------------------------------------
extern "C" void kernel_launch(void* const* d_in, const int* in_sizes, int n_in,
                              void* d_out, int out_size) {
    const int4*   idx4 = (const int4*)d_in[0];    // [B, N, 3] int32
    const float4* val4 = (const float4*)d_in[1];  // [B, N] float32
    float* out = (float*)d_out;                   // tv[8] ++ mse[8]

    zero_kernel<<<2048, 1024>>>(out, out_size);

    // Scatter with Programmatic Dependent Launch: launches while zero drains,
    // loads inputs, then griddepsyncs before touching the grid.
    cudaLaunchConfig_t cfg = {};
    cfg.gridDim  = dim3(2048);
    cfg.blockDim = dim3(256);
    cfg.dynamicSmemBytes = 0;
    cfg.stream = 0;
    cudaLaunchAttribute at[1];
    at[0].id = cudaLaunchAttributeProgrammaticStreamSerialization;
    at[0].val.programmaticStreamSerializationAllowed = 1;
    cfg.attrs = at;
    cfg.numAttrs = 1;
    cudaLaunchKernelEx(&cfg, scatter_kernel, idx4, val4);

    reduce_kernel<<<2048, 128>>>(out);            // 8b x 16jc x 16ic strips
}